// round 4
// baseline (speedup 1.0000x reference)
#include <cuda_runtime.h>
#include <math.h>

#define NN 325
#define BB 64
#define HH 64
#define KT 16

// ---------------- device scratch --------------------------------------------
// g_M = [S1, S2, Q1, Q2], Q = 2*S^2 - I
__device__ float g_M[4 * NN * NN];
__device__ float g_rs[NN];
__device__ float g_cs[NN];
__device__ float g_xx[NN * BB];
__device__ float g_xxcheb[4 * NN * BB];
__device__ float g_x1cheb[4 * NN * HH * BB];
__device__ float g_hcheb[4 * NN * HH * BB];
__device__ float g_h0a[NN * HH * BB];
__device__ float g_h0b[NN * HH * BB];
__device__ float g_h1a[NN * HH * BB];
__device__ float g_h1b[NN * HH * BB];
__device__ float g_u[NN * HH * BB];
__device__ float g_rh[NN * HH * BB];

// ---------------- f32x2 helpers ----------------------------------------------
__device__ __forceinline__ void ffma2(unsigned long long& d, unsigned long long a,
                                      unsigned long long b) {
    asm("fma.rn.f32x2 %0, %1, %2, %0;" : "+l"(d) : "l"(a), "l"(b));
}
__device__ __forceinline__ float2 unpack2(unsigned long long v) {
    float2 r;
    asm("mov.b64 {%0, %1}, %2;" : "=f"(r.x), "=f"(r.y) : "l"(v));
    return r;
}

// ---------------- support construction --------------------------------------
__global__ void sums_kernel(const float* __restrict__ adj, float* __restrict__ rs,
                            float* __restrict__ cs) {
    int n = blockIdx.x * blockDim.x + threadIdx.x;
    if (n < NN) {
        float r = 0.f, c = 0.f;
        for (int j = 0; j < NN; j++) {
            r += adj[(long)n * NN + j];
            c += adj[(long)j * NN + n];
        }
        rs[n] = r;
        cs[n] = c;
    }
}

__global__ void build_S_kernel(const float* __restrict__ adj, const float* __restrict__ rs,
                               const float* __restrict__ cs, float* __restrict__ M) {
    int i = blockIdx.x * blockDim.x + threadIdx.x;
    if (i < NN * NN) {
        int r = i / NN, c = i % NN;
        M[i] = adj[(long)c * NN + r] / rs[c];          // S1
        M[NN * NN + i] = adj[i] / cs[c];               // S2
    }
}

// Q_s = 2 * S_s @ S_s - I   (one-time)
__global__ void ssq_kernel(const float* __restrict__ M, float* __restrict__ Q) {
    const int s = blockIdx.z;
    const float* S = M + (long)s * NN * NN;
    float* Qp = Q + (long)s * NN * NN;
    __shared__ float As[16][17], Bs[16][17];
    int ty = threadIdx.y, tx = threadIdx.x;
    int row = blockIdx.y * 16 + ty, col = blockIdx.x * 16 + tx;
    float acc = 0.f;
    for (int k0 = 0; k0 < NN; k0 += 16) {
        As[ty][tx] = (row < NN && k0 + tx < NN) ? S[(long)row * NN + k0 + tx] : 0.f;
        Bs[ty][tx] = (k0 + ty < NN && col < NN) ? S[(long)(k0 + ty) * NN + col] : 0.f;
        __syncthreads();
#pragma unroll
        for (int kk = 0; kk < 16; kk++) acc += As[ty][kk] * Bs[kk][tx];
        __syncthreads();
    }
    if (row < NN && col < NN)
        Qp[(long)row * NN + col] = 2.f * acc - (row == col ? 1.f : 0.f);
}

// ---------------- packing ----------------------------------------------------
__global__ void pack_state_kernel(const float* __restrict__ st, float* __restrict__ h) {
    int i = blockIdx.x * blockDim.x + threadIdx.x;
    if (i < NN * HH * BB) {
        int b = i % BB;
        int nc = i / BB;
        h[i] = st[(long)b * NN * HH + nc];
    }
}

__global__ void pack_x_kernel(const float* __restrict__ inp, float* __restrict__ xx) {
    int i = blockIdx.x * blockDim.x + threadIdx.x;
    if (i < NN * BB) {
        int n = i / BB, b = i % BB;
        xx[i] = inp[(long)b * NN + n];
    }
}

__global__ void zero_kernel(float* __restrict__ y, int n) {
    int i = blockIdx.x * blockDim.x + threadIdx.x;
    if (i < n) y[i] = 0.f;
}

// ---------------- f32x2 SpMM: Y = M[z&3] @ X[z>>2] ---------------------------
// matrix zmat = z&3 in {S1,S2,Q1,Q2}; input zin = z>>2 selects X0/X1, Y0/Y1.
// Output written at Ysel + slot(zmat)*slotstride, slot = (zmat&1)*2 + (zmat>>1).
__global__ void __launch_bounds__(128) smm_kernel(
    const float* __restrict__ Mbase,
    const float* __restrict__ X0, const float* __restrict__ X1,
    float* __restrict__ Y0, float* __restrict__ Y1,
    long slotstride, int J) {
    const int z = blockIdx.z;
    const int zmat = z & 3;
    const float* S = Mbase + (long)zmat * NN * NN;
    const float* Xp = (z >> 2) ? X1 : X0;
    const int slot = (zmat & 1) * 2 + (zmat >> 1);
    float* Yp = ((z >> 2) ? Y1 : Y0) + (long)slot * slotstride;

    __shared__ __align__(16) float Sdup[2][KT][140];  // dup'd rows: 128 used, pad 140
    __shared__ __align__(16) float Xsub[2][KT][128];

    const int tid = threadIdx.x;
    const int n0 = blockIdx.y * 64;
    const int j0 = blockIdx.x * 128;
    const int tc = tid & 15;
    const int tr = tid >> 4;

    const int li = tid >> 4;        // S rows li + 8*ph
    const int lkk = tid & 15;       // S k within tile
    const int xkk = tid >> 5;       // X rows xkk + 4*ph
    const int xj = (tid & 31) * 4;  // X col

    unsigned long long acc[8][4];
#pragma unroll
    for (int i = 0; i < 8; i++)
#pragma unroll
        for (int j = 0; j < 4; j++) acc[i][j] = 0ULL;

    float sReg[8];
    float4 xReg[4];
    const bool xjok = (j0 + xj) < J;

    // ---- prefetch tile 0 ----
    {
        int k = lkk;
        bool kok = k < NN;
#pragma unroll
        for (int ph = 0; ph < 8; ph++) {
            int n = n0 + li + ph * 8;
            sReg[ph] = (kok && n < NN) ? S[(long)n * NN + k] : 0.f;
        }
#pragma unroll
        for (int ph = 0; ph < 4; ph++) {
            int kx = xkk + ph * 4;
            float4 v = make_float4(0.f, 0.f, 0.f, 0.f);
            if (kx < NN && xjok) v = *reinterpret_cast<const float4*>(&Xp[(long)kx * J + j0 + xj]);
            xReg[ph] = v;
        }
#pragma unroll
        for (int ph = 0; ph < 8; ph++)
            *reinterpret_cast<float2*>(&Sdup[0][lkk][2 * (li + ph * 8)]) =
                make_float2(sReg[ph], sReg[ph]);
#pragma unroll
        for (int ph = 0; ph < 4; ph++)
            *reinterpret_cast<float4*>(&Xsub[0][xkk + ph * 4][xj]) = xReg[ph];
    }
    __syncthreads();

    const int T = (NN + KT - 1) / KT;  // 21
    for (int t = 0; t < T; t++) {
        const int buf = t & 1;
        const int k0n = (t + 1) * KT;
        if (t + 1 < T) {
            int k = k0n + lkk;
            bool kok = k < NN;
#pragma unroll
            for (int ph = 0; ph < 8; ph++) {
                int n = n0 + li + ph * 8;
                sReg[ph] = (kok && n < NN) ? S[(long)n * NN + k] : 0.f;
            }
#pragma unroll
            for (int ph = 0; ph < 4; ph++) {
                int kx = k0n + xkk + ph * 4;
                float4 v = make_float4(0.f, 0.f, 0.f, 0.f);
                if (kx < NN && xjok)
                    v = *reinterpret_cast<const float4*>(&Xp[(long)kx * J + j0 + xj]);
                xReg[ph] = v;
            }
        }
#pragma unroll
        for (int kk = 0; kk < KT; kk++) {
            ulonglong2 a01 = *reinterpret_cast<const ulonglong2*>(&Sdup[buf][kk][tr * 16]);
            ulonglong2 a23 = *reinterpret_cast<const ulonglong2*>(&Sdup[buf][kk][tr * 16 + 4]);
            ulonglong2 a45 = *reinterpret_cast<const ulonglong2*>(&Sdup[buf][kk][tr * 16 + 8]);
            ulonglong2 a67 = *reinterpret_cast<const ulonglong2*>(&Sdup[buf][kk][tr * 16 + 12]);
            ulonglong2 b03 = *reinterpret_cast<const ulonglong2*>(&Xsub[buf][kk][tc * 8]);
            ulonglong2 b47 = *reinterpret_cast<const ulonglong2*>(&Xsub[buf][kk][tc * 8 + 4]);
            unsigned long long a[8] = {a01.x, a01.y, a23.x, a23.y, a45.x, a45.y, a67.x, a67.y};
            unsigned long long b[4] = {b03.x, b03.y, b47.x, b47.y};
#pragma unroll
            for (int i = 0; i < 8; i++)
#pragma unroll
                for (int j = 0; j < 4; j++) ffma2(acc[i][j], a[i], b[j]);
        }
        __syncthreads();
        if (t + 1 < T) {
            const int nb = buf ^ 1;
#pragma unroll
            for (int ph = 0; ph < 8; ph++)
                *reinterpret_cast<float2*>(&Sdup[nb][lkk][2 * (li + ph * 8)]) =
                    make_float2(sReg[ph], sReg[ph]);
#pragma unroll
            for (int ph = 0; ph < 4; ph++)
                *reinterpret_cast<float4*>(&Xsub[nb][xkk + ph * 4][xj]) = xReg[ph];
            __syncthreads();
        }
    }

#pragma unroll
    for (int i = 0; i < 8; i++) {
        int n = n0 + tr * 8 + i;
        if (n < NN) {
            int jj = j0 + tc * 8;
            if (jj < J) {
                float2 p0 = unpack2(acc[i][0]);
                float2 p1 = unpack2(acc[i][1]);
                float2 p2 = unpack2(acc[i][2]);
                float2 p3 = unpack2(acc[i][3]);
                *reinterpret_cast<float4*>(&Yp[(long)n * J + jj]) =
                    make_float4(p0.x, p0.y, p1.x, p1.y);
                *reinterpret_cast<float4*>(&Yp[(long)n * J + jj + 4]) =
                    make_float4(p2.x, p2.y, p3.x, p3.y);
            }
        }
    }
}

// ---------------- f32x2 dense xs@W with fused activation ---------------------
// One block per node n. mode 0: gate; mode 1: candidate (+optional out proj).
__global__ void __launch_bounds__(128) dense_kernel(
    const float* __restrict__ x0x, const float* __restrict__ xcheb, int Cx,
    const float* __restrict__ h0, const float* __restrict__ hcheb,
    const float* __restrict__ W, const float* __restrict__ bias, int O, int K,
    int mode,
    float* __restrict__ rh_out, float* __restrict__ u_out,
    const float* __restrict__ u_in, const float* __restrict__ h_old,
    float* __restrict__ h_new,
    const float* __restrict__ Wfc, const float* __restrict__ bfc,
    float* __restrict__ outp) {
    const int n = blockIdx.x;
    const int tid = threadIdx.x;
    const int tc = tid & 15;
    const int tr = tid >> 4;

    __shared__ __align__(16) float Adup[2][KT][136];  // dup'd batch: 128 used
    __shared__ __align__(16) float Wsh[2][KT][128];
    __shared__ float red[16][64];

    unsigned long long acc[8][4];
#pragma unroll
    for (int i = 0; i < 8; i++)
#pragma unroll
        for (int j = 0; j < 4; j++) acc[i][j] = 0ULL;

    const int akk = tid >> 3;        // 0..15 (A row, W row)
    const int ab = (tid & 7) * 8;    // A col base (8 floats)
    const int ob = (tid & 7) * 16;   // W col base (4 float4)

    float4 aR[2], wR[4];

    {
        int k = akk;
        aR[0] = make_float4(0.f, 0.f, 0.f, 0.f);
        aR[1] = make_float4(0.f, 0.f, 0.f, 0.f);
        if (k < K) {
            int c = k / 5, m = k % 5;
            const float* p;
            if (c < Cx) {
                p = (m == 0) ? (x0x + ((long)n * Cx + c) * BB)
                             : (xcheb + (((long)(m - 1) * NN + n) * Cx + c) * BB);
            } else {
                int ch = c - Cx;
                p = (m == 0) ? (h0 + ((long)n * HH + ch) * BB)
                             : (hcheb + (((long)(m - 1) * NN + n) * HH + ch) * BB);
            }
            aR[0] = *reinterpret_cast<const float4*>(&p[ab]);
            aR[1] = *reinterpret_cast<const float4*>(&p[ab + 4]);
        }
#pragma unroll
        for (int q = 0; q < 4; q++) {
            wR[q] = make_float4(0.f, 0.f, 0.f, 0.f);
            if (k < K && ob < O)
                wR[q] = *reinterpret_cast<const float4*>(&W[(long)k * O + ob + q * 4]);
        }
        const float* av = reinterpret_cast<const float*>(aR);
#pragma unroll
        for (int q = 0; q < 8; q++)
            *reinterpret_cast<float2*>(&Adup[0][akk][2 * (ab + q)]) = make_float2(av[q], av[q]);
#pragma unroll
        for (int q = 0; q < 4; q++)
            *reinterpret_cast<float4*>(&Wsh[0][akk][ob + q * 4]) = wR[q];
    }
    __syncthreads();

    const int T = (K + KT - 1) / KT;
    for (int t = 0; t < T; t++) {
        const int buf = t & 1;
        const int k0n = (t + 1) * KT;
        if (t + 1 < T) {
            int k = k0n + akk;
            aR[0] = make_float4(0.f, 0.f, 0.f, 0.f);
            aR[1] = make_float4(0.f, 0.f, 0.f, 0.f);
            if (k < K) {
                int c = k / 5, m = k % 5;
                const float* p;
                if (c < Cx) {
                    p = (m == 0) ? (x0x + ((long)n * Cx + c) * BB)
                                 : (xcheb + (((long)(m - 1) * NN + n) * Cx + c) * BB);
                } else {
                    int ch = c - Cx;
                    p = (m == 0) ? (h0 + ((long)n * HH + ch) * BB)
                                 : (hcheb + (((long)(m - 1) * NN + n) * HH + ch) * BB);
                }
                aR[0] = *reinterpret_cast<const float4*>(&p[ab]);
                aR[1] = *reinterpret_cast<const float4*>(&p[ab + 4]);
            }
#pragma unroll
            for (int q = 0; q < 4; q++) {
                wR[q] = make_float4(0.f, 0.f, 0.f, 0.f);
                if (k < K && ob < O)
                    wR[q] = *reinterpret_cast<const float4*>(&W[(long)k * O + ob + q * 4]);
            }
        }
#pragma unroll
        for (int kk = 0; kk < KT; kk++) {
            ulonglong2 a01 = *reinterpret_cast<const ulonglong2*>(&Adup[buf][kk][tr * 16]);
            ulonglong2 a23 = *reinterpret_cast<const ulonglong2*>(&Adup[buf][kk][tr * 16 + 4]);
            ulonglong2 a45 = *reinterpret_cast<const ulonglong2*>(&Adup[buf][kk][tr * 16 + 8]);
            ulonglong2 a67 = *reinterpret_cast<const ulonglong2*>(&Adup[buf][kk][tr * 16 + 12]);
            ulonglong2 b03 = *reinterpret_cast<const ulonglong2*>(&Wsh[buf][kk][tc * 8]);
            ulonglong2 b47 = *reinterpret_cast<const ulonglong2*>(&Wsh[buf][kk][tc * 8 + 4]);
            unsigned long long a[8] = {a01.x, a01.y, a23.x, a23.y, a45.x, a45.y, a67.x, a67.y};
            unsigned long long b[4] = {b03.x, b03.y, b47.x, b47.y};
#pragma unroll
            for (int i = 0; i < 8; i++)
#pragma unroll
                for (int j = 0; j < 4; j++) ffma2(acc[i][j], a[i], b[j]);
        }
        __syncthreads();
        if (t + 1 < T) {
            const int nb = buf ^ 1;
            const float* av = reinterpret_cast<const float*>(aR);
#pragma unroll
            for (int q = 0; q < 8; q++)
                *reinterpret_cast<float2*>(&Adup[nb][akk][2 * (ab + q)]) =
                    make_float2(av[q], av[q]);
#pragma unroll
            for (int q = 0; q < 4; q++)
                *reinterpret_cast<float4*>(&Wsh[nb][akk][ob + q * 4]) = wR[q];
            __syncthreads();
        }
    }

    // unpack accumulators: accf[i][j], i=batch row, j=output col
    float accf[8][8];
#pragma unroll
    for (int i = 0; i < 8; i++) {
#pragma unroll
        for (int jp = 0; jp < 4; jp++) {
            float2 v = unpack2(acc[i][jp]);
            accf[i][2 * jp] = v.x;
            accf[i][2 * jp + 1] = v.y;
        }
    }

    if (mode == 0) {
#pragma unroll
        for (int j = 0; j < 8; j++) {
            int o = tc * 8 + j;
            if (o < O) {
                float bo = bias[o];
                float s[8];
#pragma unroll
                for (int i = 0; i < 8; i++)
                    s[i] = 1.f / (1.f + expf(-(accf[i][j] + bo)));
                if (o < HH) {
                    long base = ((long)n * HH + o) * BB + tr * 8;
                    float4 hh0 = *reinterpret_cast<const float4*>(&h_old[base]);
                    float4 hh1 = *reinterpret_cast<const float4*>(&h_old[base + 4]);
                    *reinterpret_cast<float4*>(&rh_out[base]) =
                        make_float4(s[0] * hh0.x, s[1] * hh0.y, s[2] * hh0.z, s[3] * hh0.w);
                    *reinterpret_cast<float4*>(&rh_out[base + 4]) =
                        make_float4(s[4] * hh1.x, s[5] * hh1.y, s[6] * hh1.z, s[7] * hh1.w);
                } else {
                    long base = ((long)n * HH + (o - HH)) * BB + tr * 8;
                    *reinterpret_cast<float4*>(&u_out[base]) = make_float4(s[0], s[1], s[2], s[3]);
                    *reinterpret_cast<float4*>(&u_out[base + 4]) = make_float4(s[4], s[5], s[6], s[7]);
                }
            }
        }
    } else {
        float outacc[8];
#pragma unroll
        for (int i = 0; i < 8; i++) outacc[i] = 0.f;
#pragma unroll
        for (int j = 0; j < 8; j++) {
            int o = tc * 8 + j;
            if (o < O) {
                float bo = bias[o];
                long base = ((long)n * HH + o) * BB + tr * 8;
                float4 uu0 = *reinterpret_cast<const float4*>(&u_in[base]);
                float4 uu1 = *reinterpret_cast<const float4*>(&u_in[base + 4]);
                float4 hh0 = *reinterpret_cast<const float4*>(&h_old[base]);
                float4 hh1 = *reinterpret_cast<const float4*>(&h_old[base + 4]);
                float c0 = tanhf(accf[0][j] + bo), c1 = tanhf(accf[1][j] + bo);
                float c2 = tanhf(accf[2][j] + bo), c3 = tanhf(accf[3][j] + bo);
                float c4 = tanhf(accf[4][j] + bo), c5 = tanhf(accf[5][j] + bo);
                float c6 = tanhf(accf[6][j] + bo), c7 = tanhf(accf[7][j] + bo);
                float4 v0, v1;
                v0.x = uu0.x * hh0.x + (1.f - uu0.x) * c0;
                v0.y = uu0.y * hh0.y + (1.f - uu0.y) * c1;
                v0.z = uu0.z * hh0.z + (1.f - uu0.z) * c2;
                v0.w = uu0.w * hh0.w + (1.f - uu0.w) * c3;
                v1.x = uu1.x * hh1.x + (1.f - uu1.x) * c4;
                v1.y = uu1.y * hh1.y + (1.f - uu1.y) * c5;
                v1.z = uu1.z * hh1.z + (1.f - uu1.z) * c6;
                v1.w = uu1.w * hh1.w + (1.f - uu1.w) * c7;
                *reinterpret_cast<float4*>(&h_new[base]) = v0;
                *reinterpret_cast<float4*>(&h_new[base + 4]) = v1;
                if (outp) {
                    float wf = Wfc[o];
                    outacc[0] += v0.x * wf; outacc[1] += v0.y * wf;
                    outacc[2] += v0.z * wf; outacc[3] += v0.w * wf;
                    outacc[4] += v1.x * wf; outacc[5] += v1.y * wf;
                    outacc[6] += v1.z * wf; outacc[7] += v1.w * wf;
                }
            }
        }
        if (outp) {
#pragma unroll
            for (int i = 0; i < 8; i++) red[tc][tr * 8 + i] = outacc[i];
            __syncthreads();
            if (tid < 64) {
                float s = bfc[0];
#pragma unroll
                for (int q = 0; q < 16; q++) s += red[q][tid];
                outp[(long)tid * NN + n] = s;
            }
        }
    }
}

// ---------------- host orchestration -----------------------------------------
static inline void smm_launch(const float* M,
                              const float* X0, const float* X1,
                              float* Y0, float* Y1,
                              long slotstride, int J, int nz) {
    dim3 grid((J + 127) / 128, (NN + 63) / 64, nz);
    smm_kernel<<<grid, 128>>>(M, X0, X1, Y0, Y1, slotstride, J);
}

extern "C" void kernel_launch(void* const* d_in, const int* in_sizes, int n_in,
                              void* d_out, int out_size) {
    const float* inputs = (const float*)d_in[0];
    const float* init_state = (const float*)d_in[1];
    const float* adj = (const float*)d_in[2];
    const float* Wg0 = (const float*)d_in[3];
    const float* bg0 = (const float*)d_in[4];
    const float* Wc0 = (const float*)d_in[5];
    const float* bc0 = (const float*)d_in[6];
    const float* Wg1 = (const float*)d_in[7];
    const float* bg1 = (const float*)d_in[8];
    const float* Wc1 = (const float*)d_in[9];
    const float* bc1 = (const float*)d_in[10];
    const float* Wfc = (const float*)d_in[11];
    const float* bfc = (const float*)d_in[12];
    float* out = (float*)d_out;

    void* p;
    cudaGetSymbolAddress(&p, g_M);      float* M = (float*)p;
    cudaGetSymbolAddress(&p, g_rs);     float* rs = (float*)p;
    cudaGetSymbolAddress(&p, g_cs);     float* cs = (float*)p;
    cudaGetSymbolAddress(&p, g_xx);     float* xx = (float*)p;
    cudaGetSymbolAddress(&p, g_xxcheb); float* xxcheb = (float*)p;
    cudaGetSymbolAddress(&p, g_x1cheb); float* x1cheb = (float*)p;
    cudaGetSymbolAddress(&p, g_hcheb);  float* hcheb = (float*)p;
    cudaGetSymbolAddress(&p, g_h0a);    float* h0a = (float*)p;
    cudaGetSymbolAddress(&p, g_h0b);    float* h0b = (float*)p;
    cudaGetSymbolAddress(&p, g_h1a);    float* h1a = (float*)p;
    cudaGetSymbolAddress(&p, g_h1b);    float* h1b = (float*)p;
    cudaGetSymbolAddress(&p, g_u);      float* u = (float*)p;
    cudaGetSymbolAddress(&p, g_rh);     float* rh = (float*)p;

    const long hs = (long)NN * HH * BB;
    const long xs0 = (long)NN * BB;
    const int nelem = NN * HH * BB;

    // one-time setup
    sums_kernel<<<(NN + 255) / 256, 256>>>(adj, rs, cs);
    build_S_kernel<<<(NN * NN + 255) / 256, 256>>>(adj, rs, cs, M);
    {
        dim3 g((NN + 15) / 16, (NN + 15) / 16, 2);
        ssq_kernel<<<g, dim3(16, 16)>>>(M, M + 2L * NN * NN);
    }

    pack_state_kernel<<<(nelem + 255) / 256, 256>>>(init_state, h0a);
    pack_state_kernel<<<(nelem + 255) / 256, 256>>>(init_state + (long)BB * NN * HH, h1a);

    zero_kernel<<<(BB * NN + 255) / 256, 256>>>(out, BB * NN);

    for (int t = 0; t < 12; t++) {
        float* h0_old = (t & 1) ? h0b : h0a;
        float* h0_new = (t & 1) ? h0a : h0b;
        float* h1_old = (t & 1) ? h1b : h1a;
        float* h1_new = (t & 1) ? h1a : h1b;

        // ---- layer 0 ----
        pack_x_kernel<<<(NN * BB + 255) / 256, 256>>>(inputs + (long)t * BB * NN, xx);

        // x-part cheb: all 4 mats in one launch (J=64)
        smm_launch(M, xx, 0, xxcheb, 0, xs0, BB, 4);

        // gate0: h cheb on h0_old (4 mats, one launch)
        smm_launch(M, h0_old, 0, hcheb, 0, hs, HH * BB, 4);
        dense_kernel<<<NN, 128>>>(xx, xxcheb, 1, h0_old, hcheb, Wg0, bg0, 2 * HH, 325, 0,
                                  rh, u, 0, h0_old, 0, 0, 0, 0);

        // cand0: h cheb on r*h
        smm_launch(M, rh, 0, hcheb, 0, hs, HH * BB, 4);
        dense_kernel<<<NN, 128>>>(xx, xxcheb, 1, rh, hcheb, Wc0, bc0, HH, 325, 1,
                                  0, 0, u, h0_old, h0_new, 0, 0, 0);

        // ---- layer 1: x1cheb (on h0_new) + gate1 cheb (on h1_old), z=8 ----
        smm_launch(M, h0_new, h1_old, x1cheb, hcheb, hs, HH * BB, 8);
        dense_kernel<<<NN, 128>>>(h0_new, x1cheb, HH, h1_old, hcheb, Wg1, bg1, 2 * HH, 640, 0,
                                  rh, u, 0, h1_old, 0, 0, 0, 0);

        // cand1
        smm_launch(M, rh, 0, hcheb, 0, hs, HH * BB, 4);
        dense_kernel<<<NN, 128>>>(h0_new, x1cheb, HH, rh, hcheb, Wc1, bc1, HH, 640, 1,
                                  0, 0, u, h1_old, h1_new, Wfc, bfc,
                                  out + (long)(t + 1) * BB * NN);
    }
}

// round 5
// speedup vs baseline: 1.4352x; 1.4352x over previous
#include <cuda_runtime.h>
#include <cuda_bf16.h>
#include <math.h>
#include <stdint.h>

#define NN 325
#define NP 336   // padded row stride for S matrices (multiple of 8)
#define BB 64
#define HH 64
#define KT 16

// ---------------- device scratch --------------------------------------------
// g_M = [S1, S2, Q1, Q2] fp32, padded stride NP. Q = 2*S^2 - I.
__device__ float g_M[4 * NN * NP];
__device__ __nv_bfloat16 g_Shi[4 * NN * NP];
__device__ __nv_bfloat16 g_Slo[4 * NN * NP];
__device__ float g_rs[NN];
__device__ float g_cs[NN];
__device__ float g_xx[NN * BB];
__device__ float g_xxcheb[4 * NN * BB];
__device__ float g_x1cheb[4 * NN * HH * BB];
__device__ float g_hcheb[4 * NN * HH * BB];
__device__ float g_h0a[NN * HH * BB];
__device__ float g_h0b[NN * HH * BB];
__device__ float g_h1a[NN * HH * BB];
__device__ float g_h1b[NN * HH * BB];
__device__ float g_u[NN * HH * BB];
__device__ float g_rh[NN * HH * BB];

// ---------------- helpers ----------------------------------------------------
__device__ __forceinline__ uint32_t pack_hi2(float a, float b, uint32_t& lo) {
    __nv_bfloat16 ha = __float2bfloat16(a), hb = __float2bfloat16(b);
    float ra = a - __bfloat162float(ha);
    float rb = b - __bfloat162float(hb);
    __nv_bfloat162 h; h.x = ha; h.y = hb;
    __nv_bfloat162 l; l.x = __float2bfloat16(ra); l.y = __float2bfloat16(rb);
    lo = *reinterpret_cast<uint32_t*>(&l);
    return *reinterpret_cast<uint32_t*>(&h);
}

__device__ __forceinline__ void mma_bf16(float* c, uint32_t a0, uint32_t a1,
                                         uint32_t a2, uint32_t a3,
                                         uint32_t b0, uint32_t b1) {
    asm volatile(
        "mma.sync.aligned.m16n8k16.row.col.f32.bf16.bf16.f32 "
        "{%0,%1,%2,%3}, {%4,%5,%6,%7}, {%8,%9}, {%0,%1,%2,%3};"
        : "+f"(c[0]), "+f"(c[1]), "+f"(c[2]), "+f"(c[3])
        : "r"(a0), "r"(a1), "r"(a2), "r"(a3), "r"(b0), "r"(b1));
}

// ---------------- support construction --------------------------------------
__global__ void sums_kernel(const float* __restrict__ adj, float* __restrict__ rs,
                            float* __restrict__ cs) {
    int n = blockIdx.x * blockDim.x + threadIdx.x;
    if (n < NN) {
        float r = 0.f, c = 0.f;
        for (int j = 0; j < NN; j++) {
            r += adj[(long)n * NN + j];
            c += adj[(long)j * NN + n];
        }
        rs[n] = r;
        cs[n] = c;
    }
}

__global__ void build_S_kernel(const float* __restrict__ adj, const float* __restrict__ rs,
                               const float* __restrict__ cs, float* __restrict__ M) {
    int i = blockIdx.x * blockDim.x + threadIdx.x;
    if (i < NN * NP) {
        int r = i / NP, c = i % NP;
        float s1 = 0.f, s2 = 0.f;
        if (c < NN) {
            s1 = adj[(long)c * NN + r] / rs[c];
            s2 = adj[(long)r * NN + c] / cs[c];
        }
        M[i] = s1;
        M[(long)NN * NP + i] = s2;
    }
}

// Q_s = 2 * S_s @ S_s - I (padded cols -> 0)
__global__ void ssq_kernel(const float* __restrict__ M, float* __restrict__ Q) {
    const int s = blockIdx.z;
    const float* S = M + (long)s * NN * NP;
    float* Qp = Q + (long)s * NN * NP;
    __shared__ float As[16][17], Bs[16][17];
    int ty = threadIdx.y, tx = threadIdx.x;
    int row = blockIdx.y * 16 + ty, col = blockIdx.x * 16 + tx;
    float acc = 0.f;
    for (int k0 = 0; k0 < NN; k0 += 16) {
        As[ty][tx] = (row < NN && k0 + tx < NN) ? S[(long)row * NP + k0 + tx] : 0.f;
        Bs[ty][tx] = (k0 + ty < NN && col < NN) ? S[(long)(k0 + ty) * NP + col] : 0.f;
        __syncthreads();
#pragma unroll
        for (int kk = 0; kk < 16; kk++) acc += As[ty][kk] * Bs[kk][tx];
        __syncthreads();
    }
    if (row < NN && col < NP)
        Qp[(long)row * NP + col] = (col < NN) ? (2.f * acc - (row == col ? 1.f : 0.f)) : 0.f;
}

__global__ void split_kernel(const float* __restrict__ M, __nv_bfloat16* __restrict__ hi,
                             __nv_bfloat16* __restrict__ lo, int n) {
    int i = blockIdx.x * blockDim.x + threadIdx.x;
    if (i < n) {
        float v = M[i];
        __nv_bfloat16 h = __float2bfloat16(v);
        hi[i] = h;
        lo[i] = __float2bfloat16(v - __bfloat162float(h));
    }
}

// ---------------- packing ----------------------------------------------------
__global__ void pack_state_kernel(const float* __restrict__ st, float* __restrict__ h) {
    int i = blockIdx.x * blockDim.x + threadIdx.x;
    if (i < NN * HH * BB) {
        int b = i % BB;
        int nc = i / BB;
        h[i] = st[(long)b * NN * HH + nc];
    }
}

__global__ void pack_x_kernel(const float* __restrict__ inp, float* __restrict__ xx) {
    int i = blockIdx.x * blockDim.x + threadIdx.x;
    if (i < NN * BB) {
        int n = i / BB, b = i % BB;
        xx[i] = inp[(long)b * NN + n];
    }
}

__global__ void zero_kernel(float* __restrict__ y, int n) {
    int i = blockIdx.x * blockDim.x + threadIdx.x;
    if (i < n) y[i] = 0.f;
}

// ---------------- tensor-core SpMM: Y = M[z&3] @ X[z>>2] ---------------------
// slot(zmat) = (zmat&1)*2 + (zmat>>1)  -> hcheb slot order [S1x, Q1x, S2x, Q2x]
// bf16-split: Y = Shi@Xhi + Shi@Xlo + Slo@Xhi, fp32 accumulate.
// Block 256 thr (8 warps), tile 64(m/n-rows) x 128(j), K-chunk 16, double-buffered.
__global__ void __launch_bounds__(256) smm_tc_kernel(
    const __nv_bfloat16* __restrict__ Shi_g, const __nv_bfloat16* __restrict__ Slo_g,
    const float* __restrict__ X0, const float* __restrict__ X1,
    float* __restrict__ Y0, float* __restrict__ Y1,
    long slotstride, int J) {
    const int z = blockIdx.z;
    const int zmat = z & 3;
    const int slot = (zmat & 1) * 2 + (zmat >> 1);
    const __nv_bfloat16* Sh = Shi_g + (long)zmat * NN * NP;
    const __nv_bfloat16* Sl = Slo_g + (long)zmat * NN * NP;
    const float* Xp = (z >> 2) ? X1 : X0;
    float* Yp = ((z >> 2) ? Y1 : Y0) + (long)slot * slotstride;

    // smem as u32 words: [buf][hi/lo][row][k-u32(=2 bf16)], row stride 10 u32 (pad)
    __shared__ uint32_t sS[2][2][64][10];
    __shared__ uint32_t sX[2][2][128][10];

    const int tid = threadIdx.x;
    const int lane = tid & 31;
    const int wid = tid >> 5;
    const int warp_m = wid & 1;         // 0..1
    const int warp_n = wid >> 1;        // 0..3
    const int m_base = warp_m * 32;
    const int n_base = warp_n * 32;
    const int n0 = blockIdx.y * 64;     // global row base
    const int j0 = blockIdx.x * 128;    // global col base

    // ---- fill thread mappings ----
    // S: thread -> (m = tid>>2, kq = (tid&3)*4)  [64 x 16 bf16]
    const int sm = tid >> 2;
    const int skq = (tid & 3) * 4;
    // X: thread -> (j = tid&127, khalf = tid>>7): 8 consecutive k rows at col j
    const int xjl = tid & 127;
    const int xkh = tid >> 7;

    float c[2][4][4];
#pragma unroll
    for (int mf = 0; mf < 2; mf++)
#pragma unroll
        for (int nf = 0; nf < 4; nf++)
#pragma unroll
            for (int q = 0; q < 4; q++) c[mf][nf][q] = 0.f;

    uint2 sHiR, sLoR;
    float xr[8];
    const bool xjok = (j0 + xjl) < J;

    // ---- prefetch chunk 0 ----
    {
        int k0 = 0;
        if (n0 + sm < NN) {
            sHiR = *reinterpret_cast<const uint2*>(&Sh[(long)(n0 + sm) * NP + k0 + skq]);
            sLoR = *reinterpret_cast<const uint2*>(&Sl[(long)(n0 + sm) * NP + k0 + skq]);
        } else {
            sHiR = make_uint2(0u, 0u);
            sLoR = make_uint2(0u, 0u);
        }
#pragma unroll
        for (int r = 0; r < 8; r++) {
            int krow = k0 + xkh * 8 + r;
            xr[r] = (krow < NN && xjok) ? Xp[(long)krow * J + j0 + xjl] : 0.f;
        }
        *reinterpret_cast<uint2*>(&sS[0][0][sm][skq >> 1]) = sHiR;
        *reinterpret_cast<uint2*>(&sS[0][1][sm][skq >> 1]) = sLoR;
#pragma unroll
        for (int pq = 0; pq < 4; pq++) {
            uint32_t lo;
            uint32_t hi = pack_hi2(xr[2 * pq], xr[2 * pq + 1], lo);
            sX[0][0][xjl][xkh * 4 + pq] = hi;
            sX[0][1][xjl][xkh * 4 + pq] = lo;
        }
    }
    __syncthreads();

    const int T = (NN + KT - 1) / KT;  // 21
    for (int t = 0; t < T; t++) {
        const int buf = t & 1;
        if (t + 1 < T) {
            int k0 = (t + 1) * KT;
            if (n0 + sm < NN) {
                sHiR = *reinterpret_cast<const uint2*>(&Sh[(long)(n0 + sm) * NP + k0 + skq]);
                sLoR = *reinterpret_cast<const uint2*>(&Sl[(long)(n0 + sm) * NP + k0 + skq]);
            } else {
                sHiR = make_uint2(0u, 0u);
                sLoR = make_uint2(0u, 0u);
            }
#pragma unroll
            for (int r = 0; r < 8; r++) {
                int krow = k0 + xkh * 8 + r;
                xr[r] = (krow < NN && xjok) ? Xp[(long)krow * J + j0 + xjl] : 0.f;
            }
        }

        // ---- MMA on buf ----
        {
            const int cidx = lane & 3;
            const int rsel = lane >> 2;
            uint32_t ahi[2][4], alo[2][4];
#pragma unroll
            for (int mf = 0; mf < 2; mf++) {
                int r0 = m_base + mf * 16 + rsel;
                ahi[mf][0] = sS[buf][0][r0][cidx];
                ahi[mf][1] = sS[buf][0][r0 + 8][cidx];
                ahi[mf][2] = sS[buf][0][r0][cidx + 4];
                ahi[mf][3] = sS[buf][0][r0 + 8][cidx + 4];
                alo[mf][0] = sS[buf][1][r0][cidx];
                alo[mf][1] = sS[buf][1][r0 + 8][cidx];
                alo[mf][2] = sS[buf][1][r0][cidx + 4];
                alo[mf][3] = sS[buf][1][r0 + 8][cidx + 4];
            }
            uint32_t bhi[4][2], blo[4][2];
#pragma unroll
            for (int nf = 0; nf < 4; nf++) {
                int col = n_base + nf * 8 + rsel;
                bhi[nf][0] = sX[buf][0][col][cidx];
                bhi[nf][1] = sX[buf][0][col][cidx + 4];
                blo[nf][0] = sX[buf][1][col][cidx];
                blo[nf][1] = sX[buf][1][col][cidx + 4];
            }
#pragma unroll
            for (int mf = 0; mf < 2; mf++)
#pragma unroll
                for (int nf = 0; nf < 4; nf++) {
                    mma_bf16(c[mf][nf], ahi[mf][0], ahi[mf][1], ahi[mf][2], ahi[mf][3],
                             bhi[nf][0], bhi[nf][1]);
                    mma_bf16(c[mf][nf], ahi[mf][0], ahi[mf][1], ahi[mf][2], ahi[mf][3],
                             blo[nf][0], blo[nf][1]);
                    mma_bf16(c[mf][nf], alo[mf][0], alo[mf][1], alo[mf][2], alo[mf][3],
                             bhi[nf][0], bhi[nf][1]);
                }
        }
        __syncthreads();
        if (t + 1 < T) {
            const int nb = buf ^ 1;
            *reinterpret_cast<uint2*>(&sS[nb][0][sm][skq >> 1]) = sHiR;
            *reinterpret_cast<uint2*>(&sS[nb][1][sm][skq >> 1]) = sLoR;
#pragma unroll
            for (int pq = 0; pq < 4; pq++) {
                uint32_t lo;
                uint32_t hi = pack_hi2(xr[2 * pq], xr[2 * pq + 1], lo);
                sX[nb][0][xjl][xkh * 4 + pq] = hi;
                sX[nb][1][xjl][xkh * 4 + pq] = lo;
            }
            __syncthreads();
        }
    }

    // ---- epilogue ----
    {
        const int rsel = lane >> 2;
        const int csel = (lane & 3) * 2;
#pragma unroll
        for (int mf = 0; mf < 2; mf++) {
#pragma unroll
            for (int nf = 0; nf < 4; nf++) {
                int row = n0 + m_base + mf * 16 + rsel;
                int col = j0 + n_base + nf * 8 + csel;
                if (col < J) {
                    if (row < NN)
                        *reinterpret_cast<float2*>(&Yp[(long)row * J + col]) =
                            make_float2(c[mf][nf][0], c[mf][nf][1]);
                    if (row + 8 < NN)
                        *reinterpret_cast<float2*>(&Yp[(long)(row + 8) * J + col]) =
                            make_float2(c[mf][nf][2], c[mf][nf][3]);
                }
            }
        }
    }
}

// ---------------- dense xs@W with fused activation (R3 FFMA version) ---------
__global__ void __launch_bounds__(128) dense_kernel(
    const float* __restrict__ x0x, const float* __restrict__ xcheb, int Cx,
    const float* __restrict__ h0, const float* __restrict__ hcheb,
    const float* __restrict__ W, const float* __restrict__ bias, int O, int K,
    int mode,
    float* __restrict__ rh_out, float* __restrict__ u_out,
    const float* __restrict__ u_in, const float* __restrict__ h_old,
    float* __restrict__ h_new,
    const float* __restrict__ Wfc, const float* __restrict__ bfc,
    float* __restrict__ outp) {
    const int n = blockIdx.x;
    const int tid = threadIdx.x;
    const int tc = tid & 15;
    const int tr = tid >> 4;

    __shared__ float Ash[2][KT][64];
    __shared__ float Wsh[2][KT][128];
    __shared__ float red[16][64];

    float acc[8][8];
#pragma unroll
    for (int i = 0; i < 8; i++)
#pragma unroll
        for (int j = 0; j < 8; j++) acc[i][j] = 0.f;

    const int akk = tid >> 3;
    const int ab = (tid & 7) * 8;
    const int ob = (tid & 7) * 16;

    float4 aR[2], wR[4];

    {
        int k = akk;
        aR[0] = make_float4(0.f, 0.f, 0.f, 0.f);
        aR[1] = make_float4(0.f, 0.f, 0.f, 0.f);
        if (k < K) {
            int c = k / 5, m = k % 5;
            const float* p;
            if (c < Cx) {
                p = (m == 0) ? (x0x + ((long)n * Cx + c) * BB)
                             : (xcheb + (((long)(m - 1) * NN + n) * Cx + c) * BB);
            } else {
                int ch = c - Cx;
                p = (m == 0) ? (h0 + ((long)n * HH + ch) * BB)
                             : (hcheb + (((long)(m - 1) * NN + n) * HH + ch) * BB);
            }
            aR[0] = *reinterpret_cast<const float4*>(&p[ab]);
            aR[1] = *reinterpret_cast<const float4*>(&p[ab + 4]);
        }
#pragma unroll
        for (int q = 0; q < 4; q++) {
            wR[q] = make_float4(0.f, 0.f, 0.f, 0.f);
            if (k < K && ob < O)
                wR[q] = *reinterpret_cast<const float4*>(&W[(long)k * O + ob + q * 4]);
        }
        *reinterpret_cast<float4*>(&Ash[0][akk][ab]) = aR[0];
        *reinterpret_cast<float4*>(&Ash[0][akk][ab + 4]) = aR[1];
#pragma unroll
        for (int q = 0; q < 4; q++)
            *reinterpret_cast<float4*>(&Wsh[0][akk][ob + q * 4]) = wR[q];
    }
    __syncthreads();

    const int T = (K + KT - 1) / KT;
    for (int t = 0; t < T; t++) {
        const int buf = t & 1;
        const int k0n = (t + 1) * KT;
        if (t + 1 < T) {
            int k = k0n + akk;
            aR[0] = make_float4(0.f, 0.f, 0.f, 0.f);
            aR[1] = make_float4(0.f, 0.f, 0.f, 0.f);
            if (k < K) {
                int c = k / 5, m = k % 5;
                const float* p;
                if (c < Cx) {
                    p = (m == 0) ? (x0x + ((long)n * Cx + c) * BB)
                                 : (xcheb + (((long)(m - 1) * NN + n) * Cx + c) * BB);
                } else {
                    int ch = c - Cx;
                    p = (m == 0) ? (h0 + ((long)n * HH + ch) * BB)
                                 : (hcheb + (((long)(m - 1) * NN + n) * HH + ch) * BB);
                }
                aR[0] = *reinterpret_cast<const float4*>(&p[ab]);
                aR[1] = *reinterpret_cast<const float4*>(&p[ab + 4]);
            }
#pragma unroll
            for (int q = 0; q < 4; q++) {
                wR[q] = make_float4(0.f, 0.f, 0.f, 0.f);
                if (k < K && ob < O)
                    wR[q] = *reinterpret_cast<const float4*>(&W[(long)k * O + ob + q * 4]);
            }
        }
#pragma unroll
        for (int kk = 0; kk < KT; kk++) {
            float4 a0 = *reinterpret_cast<const float4*>(&Ash[buf][kk][tr * 8]);
            float4 a1 = *reinterpret_cast<const float4*>(&Ash[buf][kk][tr * 8 + 4]);
            float4 w0 = *reinterpret_cast<const float4*>(&Wsh[buf][kk][tc * 8]);
            float4 w1 = *reinterpret_cast<const float4*>(&Wsh[buf][kk][tc * 8 + 4]);
            float a[8] = {a0.x, a0.y, a0.z, a0.w, a1.x, a1.y, a1.z, a1.w};
            float w[8] = {w0.x, w0.y, w0.z, w0.w, w1.x, w1.y, w1.z, w1.w};
#pragma unroll
            for (int i = 0; i < 8; i++)
#pragma unroll
                for (int j = 0; j < 8; j++) acc[i][j] += a[i] * w[j];
        }
        __syncthreads();
        if (t + 1 < T) {
            const int nb = buf ^ 1;
            *reinterpret_cast<float4*>(&Ash[nb][akk][ab]) = aR[0];
            *reinterpret_cast<float4*>(&Ash[nb][akk][ab + 4]) = aR[1];
#pragma unroll
            for (int q = 0; q < 4; q++)
                *reinterpret_cast<float4*>(&Wsh[nb][akk][ob + q * 4]) = wR[q];
            __syncthreads();
        }
    }

    if (mode == 0) {
#pragma unroll
        for (int j = 0; j < 8; j++) {
            int o = tc * 8 + j;
            if (o < O) {
                float bo = bias[o];
                float s[8];
#pragma unroll
                for (int i = 0; i < 8; i++)
                    s[i] = 1.f / (1.f + expf(-(acc[i][j] + bo)));
                if (o < HH) {
                    long base = ((long)n * HH + o) * BB + tr * 8;
                    float4 hh0 = *reinterpret_cast<const float4*>(&h_old[base]);
                    float4 hh1 = *reinterpret_cast<const float4*>(&h_old[base + 4]);
                    *reinterpret_cast<float4*>(&rh_out[base]) =
                        make_float4(s[0] * hh0.x, s[1] * hh0.y, s[2] * hh0.z, s[3] * hh0.w);
                    *reinterpret_cast<float4*>(&rh_out[base + 4]) =
                        make_float4(s[4] * hh1.x, s[5] * hh1.y, s[6] * hh1.z, s[7] * hh1.w);
                } else {
                    long base = ((long)n * HH + (o - HH)) * BB + tr * 8;
                    *reinterpret_cast<float4*>(&u_out[base]) = make_float4(s[0], s[1], s[2], s[3]);
                    *reinterpret_cast<float4*>(&u_out[base + 4]) = make_float4(s[4], s[5], s[6], s[7]);
                }
            }
        }
    } else {
        float outacc[8];
#pragma unroll
        for (int i = 0; i < 8; i++) outacc[i] = 0.f;
#pragma unroll
        for (int j = 0; j < 8; j++) {
            int o = tc * 8 + j;
            if (o < O) {
                float bo = bias[o];
                long base = ((long)n * HH + o) * BB + tr * 8;
                float4 uu0 = *reinterpret_cast<const float4*>(&u_in[base]);
                float4 uu1 = *reinterpret_cast<const float4*>(&u_in[base + 4]);
                float4 hh0 = *reinterpret_cast<const float4*>(&h_old[base]);
                float4 hh1 = *reinterpret_cast<const float4*>(&h_old[base + 4]);
                float c0 = tanhf(acc[0][j] + bo), c1 = tanhf(acc[1][j] + bo);
                float c2 = tanhf(acc[2][j] + bo), c3 = tanhf(acc[3][j] + bo);
                float c4 = tanhf(acc[4][j] + bo), c5 = tanhf(acc[5][j] + bo);
                float c6 = tanhf(acc[6][j] + bo), c7 = tanhf(acc[7][j] + bo);
                float4 v0, v1;
                v0.x = uu0.x * hh0.x + (1.f - uu0.x) * c0;
                v0.y = uu0.y * hh0.y + (1.f - uu0.y) * c1;
                v0.z = uu0.z * hh0.z + (1.f - uu0.z) * c2;
                v0.w = uu0.w * hh0.w + (1.f - uu0.w) * c3;
                v1.x = uu1.x * hh1.x + (1.f - uu1.x) * c4;
                v1.y = uu1.y * hh1.y + (1.f - uu1.y) * c5;
                v1.z = uu1.z * hh1.z + (1.f - uu1.z) * c6;
                v1.w = uu1.w * hh1.w + (1.f - uu1.w) * c7;
                *reinterpret_cast<float4*>(&h_new[base]) = v0;
                *reinterpret_cast<float4*>(&h_new[base + 4]) = v1;
                if (outp) {
                    float wf = Wfc[o];
                    outacc[0] += v0.x * wf; outacc[1] += v0.y * wf;
                    outacc[2] += v0.z * wf; outacc[3] += v0.w * wf;
                    outacc[4] += v1.x * wf; outacc[5] += v1.y * wf;
                    outacc[6] += v1.z * wf; outacc[7] += v1.w * wf;
                }
            }
        }
        if (outp) {
#pragma unroll
            for (int i = 0; i < 8; i++) red[tc][tr * 8 + i] = outacc[i];
            __syncthreads();
            if (tid < 64) {
                float s = bfc[0];
#pragma unroll
                for (int q = 0; q < 16; q++) s += red[q][tid];
                outp[(long)tid * NN + n] = s;
            }
        }
    }
}

// ---------------- host orchestration -----------------------------------------
static inline void smm_launch(const __nv_bfloat16* Shi, const __nv_bfloat16* Slo,
                              const float* X0, const float* X1,
                              float* Y0, float* Y1,
                              long slotstride, int J, int nz) {
    dim3 grid((J + 127) / 128, (NN + 63) / 64, nz);
    smm_tc_kernel<<<grid, 256>>>(Shi, Slo, X0, X1, Y0, Y1, slotstride, J);
}

extern "C" void kernel_launch(void* const* d_in, const int* in_sizes, int n_in,
                              void* d_out, int out_size) {
    const float* inputs = (const float*)d_in[0];
    const float* init_state = (const float*)d_in[1];
    const float* adj = (const float*)d_in[2];
    const float* Wg0 = (const float*)d_in[3];
    const float* bg0 = (const float*)d_in[4];
    const float* Wc0 = (const float*)d_in[5];
    const float* bc0 = (const float*)d_in[6];
    const float* Wg1 = (const float*)d_in[7];
    const float* bg1 = (const float*)d_in[8];
    const float* Wc1 = (const float*)d_in[9];
    const float* bc1 = (const float*)d_in[10];
    const float* Wfc = (const float*)d_in[11];
    const float* bfc = (const float*)d_in[12];
    float* out = (float*)d_out;

    void* p;
    cudaGetSymbolAddress(&p, g_M);      float* M = (float*)p;
    cudaGetSymbolAddress(&p, g_Shi);    __nv_bfloat16* Shi = (__nv_bfloat16*)p;
    cudaGetSymbolAddress(&p, g_Slo);    __nv_bfloat16* Slo = (__nv_bfloat16*)p;
    cudaGetSymbolAddress(&p, g_rs);     float* rs = (float*)p;
    cudaGetSymbolAddress(&p, g_cs);     float* cs = (float*)p;
    cudaGetSymbolAddress(&p, g_xx);     float* xx = (float*)p;
    cudaGetSymbolAddress(&p, g_xxcheb); float* xxcheb = (float*)p;
    cudaGetSymbolAddress(&p, g_x1cheb); float* x1cheb = (float*)p;
    cudaGetSymbolAddress(&p, g_hcheb);  float* hcheb = (float*)p;
    cudaGetSymbolAddress(&p, g_h0a);    float* h0a = (float*)p;
    cudaGetSymbolAddress(&p, g_h0b);    float* h0b = (float*)p;
    cudaGetSymbolAddress(&p, g_h1a);    float* h1a = (float*)p;
    cudaGetSymbolAddress(&p, g_h1b);    float* h1b = (float*)p;
    cudaGetSymbolAddress(&p, g_u);      float* u = (float*)p;
    cudaGetSymbolAddress(&p, g_rh);     float* rh = (float*)p;

    const long hs = (long)NN * HH * BB;
    const long xs0 = (long)NN * BB;
    const int nelem = NN * HH * BB;

    // one-time setup
    sums_kernel<<<(NN + 255) / 256, 256>>>(adj, rs, cs);
    build_S_kernel<<<(NN * NP + 255) / 256, 256>>>(adj, rs, cs, M);
    {
        dim3 g((NP + 15) / 16, (NN + 15) / 16, 2);
        ssq_kernel<<<g, dim3(16, 16)>>>(M, M + 2L * NN * NP);
    }
    split_kernel<<<(4 * NN * NP + 255) / 256, 256>>>(M, Shi, Slo, 4 * NN * NP);

    pack_state_kernel<<<(nelem + 255) / 256, 256>>>(init_state, h0a);
    pack_state_kernel<<<(nelem + 255) / 256, 256>>>(init_state + (long)BB * NN * HH, h1a);

    zero_kernel<<<(BB * NN + 255) / 256, 256>>>(out, BB * NN);

    for (int t = 0; t < 12; t++) {
        float* h0_old = (t & 1) ? h0b : h0a;
        float* h0_new = (t & 1) ? h0a : h0b;
        float* h1_old = (t & 1) ? h1b : h1a;
        float* h1_new = (t & 1) ? h1a : h1b;

        // ---- layer 0 ----
        pack_x_kernel<<<(NN * BB + 255) / 256, 256>>>(inputs + (long)t * BB * NN, xx);

        // x-part cheb: all 4 mats, one launch (J=64)
        smm_launch(Shi, Slo, xx, 0, xxcheb, 0, xs0, BB, 4);

        // gate0
        smm_launch(Shi, Slo, h0_old, 0, hcheb, 0, hs, HH * BB, 4);
        dense_kernel<<<NN, 128>>>(xx, xxcheb, 1, h0_old, hcheb, Wg0, bg0, 2 * HH, 325, 0,
                                  rh, u, 0, h0_old, 0, 0, 0, 0);

        // cand0
        smm_launch(Shi, Slo, rh, 0, hcheb, 0, hs, HH * BB, 4);
        dense_kernel<<<NN, 128>>>(xx, xxcheb, 1, rh, hcheb, Wc0, bc0, HH, 325, 1,
                                  0, 0, u, h0_old, h0_new, 0, 0, 0);

        // ---- layer 1: x1cheb (h0_new) + gate1 cheb (h1_old), z=8 ----
        smm_launch(Shi, Slo, h0_new, h1_old, x1cheb, hcheb, hs, HH * BB, 8);
        dense_kernel<<<NN, 128>>>(h0_new, x1cheb, HH, h1_old, hcheb, Wg1, bg1, 2 * HH, 640, 0,
                                  rh, u, 0, h1_old, 0, 0, 0, 0);

        // cand1
        smm_launch(Shi, Slo, rh, 0, hcheb, 0, hs, HH * BB, 4);
        dense_kernel<<<NN, 128>>>(h0_new, x1cheb, HH, rh, hcheb, Wc1, bc1, HH, 640, 1,
                                  0, 0, u, h1_old, h1_new, Wfc, bfc,
                                  out + (long)(t + 1) * BB * NN);
    }
}

// round 7
// speedup vs baseline: 1.7115x; 1.1925x over previous
#include <cuda_runtime.h>
#include <cuda_bf16.h>
#include <math.h>
#include <stdint.h>

#define NN 325
#define NP 336   // padded row stride for S matrices
#define BB 64
#define HH 64
#define KT 16
#define WKP 640  // padded K stride for pre-split weights
#define WKP2 (WKP / 2)

// ---------------- device scratch --------------------------------------------
__device__ float g_M[4 * NN * NP];
__device__ __nv_bfloat16 g_Shi[4 * NN * NP];
__device__ __nv_bfloat16 g_Slo[4 * NN * NP];
__device__ __nv_bfloat16 g_Wth[4 * 128 * WKP];
__device__ __nv_bfloat16 g_Wtl[4 * 128 * WKP];
__device__ float g_rs[NN];
__device__ float g_cs[NN];
__device__ float g_xx[NN * BB];
__device__ float g_xxcheb[4 * NN * BB];
__device__ float g_x1cheb[4 * NN * HH * BB];
__device__ float g_hcheb[4 * NN * HH * BB];
__device__ float g_h0a[NN * HH * BB];
__device__ float g_h0b[NN * HH * BB];
__device__ float g_h1a[NN * HH * BB];
__device__ float g_h1b[NN * HH * BB];
__device__ float g_u[NN * HH * BB];
__device__ float g_rh[NN * HH * BB];

// ---------------- helpers ----------------------------------------------------
__device__ __forceinline__ uint32_t pack_hi2(float a, float b, uint32_t& lo) {
    __nv_bfloat16 ha = __float2bfloat16(a), hb = __float2bfloat16(b);
    float ra = a - __bfloat162float(ha);
    float rb = b - __bfloat162float(hb);
    __nv_bfloat162 h; h.x = ha; h.y = hb;
    __nv_bfloat162 l; l.x = __float2bfloat16(ra); l.y = __float2bfloat16(rb);
    lo = *reinterpret_cast<uint32_t*>(&l);
    return *reinterpret_cast<uint32_t*>(&h);
}

__device__ __forceinline__ void mma_bf16(float* c, uint32_t a0, uint32_t a1,
                                         uint32_t a2, uint32_t a3,
                                         uint32_t b0, uint32_t b1) {
    asm volatile(
        "mma.sync.aligned.m16n8k16.row.col.f32.bf16.bf16.f32 "
        "{%0,%1,%2,%3}, {%4,%5,%6,%7}, {%8,%9}, {%0,%1,%2,%3};"
        : "+f"(c[0]), "+f"(c[1]), "+f"(c[2]), "+f"(c[3])
        : "r"(a0), "r"(a1), "r"(a2), "r"(a3), "r"(b0), "r"(b1));
}

// ---------------- support construction --------------------------------------
__global__ void sums_kernel(const float* __restrict__ adj, float* __restrict__ rs,
                            float* __restrict__ cs) {
    int n = blockIdx.x * blockDim.x + threadIdx.x;
    if (n < NN) {
        float r = 0.f, c = 0.f;
        for (int j = 0; j < NN; j++) {
            r += adj[(long)n * NN + j];
            c += adj[(long)j * NN + n];
        }
        rs[n] = r;
        cs[n] = c;
    }
}

__global__ void build_S_kernel(const float* __restrict__ adj, const float* __restrict__ rs,
                               const float* __restrict__ cs, float* __restrict__ M) {
    int i = blockIdx.x * blockDim.x + threadIdx.x;
    if (i < NN * NP) {
        int r = i / NP, c = i % NP;
        float s1 = 0.f, s2 = 0.f;
        if (c < NN) {
            s1 = adj[(long)c * NN + r] / rs[c];
            s2 = adj[(long)r * NN + c] / cs[c];
        }
        M[i] = s1;
        M[(long)NN * NP + i] = s2;
    }
}

__global__ void ssq_kernel(const float* __restrict__ M, float* __restrict__ Q) {
    const int s = blockIdx.z;
    const float* S = M + (long)s * NN * NP;
    float* Qp = Q + (long)s * NN * NP;
    __shared__ float As[16][17], Bs[16][17];
    int ty = threadIdx.y, tx = threadIdx.x;
    int row = blockIdx.y * 16 + ty, col = blockIdx.x * 16 + tx;
    float acc = 0.f;
    for (int k0 = 0; k0 < NN; k0 += 16) {
        As[ty][tx] = (row < NN && k0 + tx < NN) ? S[(long)row * NP + k0 + tx] : 0.f;
        Bs[ty][tx] = (k0 + ty < NN && col < NN) ? S[(long)(k0 + ty) * NP + col] : 0.f;
        __syncthreads();
#pragma unroll
        for (int kk = 0; kk < 16; kk++) acc += As[ty][kk] * Bs[kk][tx];
        __syncthreads();
    }
    if (row < NN && col < NP)
        Qp[(long)row * NP + col] = (col < NN) ? (2.f * acc - (row == col ? 1.f : 0.f)) : 0.f;
}

__global__ void split_kernel(const float* __restrict__ M, __nv_bfloat16* __restrict__ hi,
                             __nv_bfloat16* __restrict__ lo, int n) {
    int i = blockIdx.x * blockDim.x + threadIdx.x;
    if (i < n) {
        float v = M[i];
        __nv_bfloat16 h = __float2bfloat16(v);
        hi[i] = h;
        lo[i] = __float2bfloat16(v - __bfloat162float(h));
    }
}

// transpose + pad + split weights: hi/lo are [128][WKP]
__global__ void splitW_kernel(const float* __restrict__ W, int K, int O,
                              __nv_bfloat16* __restrict__ hi, __nv_bfloat16* __restrict__ lo) {
    int i = blockIdx.x * blockDim.x + threadIdx.x;
    if (i < 128 * WKP) {
        int o = i / WKP, k = i % WKP;
        float v = (o < O && k < K) ? W[(long)k * O + o] : 0.f;
        __nv_bfloat16 h = __float2bfloat16(v);
        hi[i] = h;
        lo[i] = __float2bfloat16(v - __bfloat162float(h));
    }
}

// ---------------- packing ----------------------------------------------------
__global__ void pack_state_kernel(const float* __restrict__ st, float* __restrict__ h) {
    int i = blockIdx.x * blockDim.x + threadIdx.x;
    if (i < NN * HH * BB) {
        int b = i % BB;
        int nc = i / BB;
        h[i] = st[(long)b * NN * HH + nc];
    }
}

__global__ void pack_x_kernel(const float* __restrict__ inp, float* __restrict__ xx) {
    int i = blockIdx.x * blockDim.x + threadIdx.x;
    if (i < NN * BB) {
        int n = i / BB, b = i % BB;
        xx[i] = inp[(long)b * NN + n];
    }
}

__global__ void zero_kernel(float* __restrict__ y, int n) {
    int i = blockIdx.x * blockDim.x + threadIdx.x;
    if (i < n) y[i] = 0.f;
}

// ---------------- tensor-core SpMM (validated in R5) --------------------------
__global__ void __launch_bounds__(256) smm_tc_kernel(
    const __nv_bfloat16* __restrict__ Shi_g, const __nv_bfloat16* __restrict__ Slo_g,
    const float* __restrict__ X0, const float* __restrict__ X1,
    float* __restrict__ Y0, float* __restrict__ Y1,
    long slotstride, int J) {
    const int z = blockIdx.z;
    const int zmat = z & 3;
    const int slot = (zmat & 1) * 2 + (zmat >> 1);
    const __nv_bfloat16* Sh = Shi_g + (long)zmat * NN * NP;
    const __nv_bfloat16* Sl = Slo_g + (long)zmat * NN * NP;
    const float* Xp = (z >> 2) ? X1 : X0;
    float* Yp = ((z >> 2) ? Y1 : Y0) + (long)slot * slotstride;

    __shared__ uint32_t sS[2][2][64][10];
    __shared__ uint32_t sX[2][2][128][10];

    const int tid = threadIdx.x;
    const int lane = tid & 31;
    const int wid = tid >> 5;
    const int warp_m = wid & 1;
    const int warp_n = wid >> 1;
    const int m_base = warp_m * 32;
    const int n_base = warp_n * 32;
    const int n0 = blockIdx.y * 64;
    const int j0 = blockIdx.x * 128;

    const int sm = tid >> 2;
    const int skq = (tid & 3) * 4;
    const int xjl = tid & 127;
    const int xkh = tid >> 7;

    float c[2][4][4];
#pragma unroll
    for (int mf = 0; mf < 2; mf++)
#pragma unroll
        for (int nf = 0; nf < 4; nf++)
#pragma unroll
            for (int q = 0; q < 4; q++) c[mf][nf][q] = 0.f;

    uint2 sHiR, sLoR;
    float xr[8];
    const bool xjok = (j0 + xjl) < J;

    {
        int k0 = 0;
        if (n0 + sm < NN) {
            sHiR = *reinterpret_cast<const uint2*>(&Sh[(long)(n0 + sm) * NP + k0 + skq]);
            sLoR = *reinterpret_cast<const uint2*>(&Sl[(long)(n0 + sm) * NP + k0 + skq]);
        } else {
            sHiR = make_uint2(0u, 0u);
            sLoR = make_uint2(0u, 0u);
        }
#pragma unroll
        for (int r = 0; r < 8; r++) {
            int krow = k0 + xkh * 8 + r;
            xr[r] = (krow < NN && xjok) ? Xp[(long)krow * J + j0 + xjl] : 0.f;
        }
        *reinterpret_cast<uint2*>(&sS[0][0][sm][skq >> 1]) = sHiR;
        *reinterpret_cast<uint2*>(&sS[0][1][sm][skq >> 1]) = sLoR;
#pragma unroll
        for (int pq = 0; pq < 4; pq++) {
            uint32_t lo;
            uint32_t hi = pack_hi2(xr[2 * pq], xr[2 * pq + 1], lo);
            sX[0][0][xjl][xkh * 4 + pq] = hi;
            sX[0][1][xjl][xkh * 4 + pq] = lo;
        }
    }
    __syncthreads();

    const int T = (NN + KT - 1) / KT;
    for (int t = 0; t < T; t++) {
        const int buf = t & 1;
        if (t + 1 < T) {
            int k0 = (t + 1) * KT;
            if (n0 + sm < NN) {
                sHiR = *reinterpret_cast<const uint2*>(&Sh[(long)(n0 + sm) * NP + k0 + skq]);
                sLoR = *reinterpret_cast<const uint2*>(&Sl[(long)(n0 + sm) * NP + k0 + skq]);
            } else {
                sHiR = make_uint2(0u, 0u);
                sLoR = make_uint2(0u, 0u);
            }
#pragma unroll
            for (int r = 0; r < 8; r++) {
                int krow = k0 + xkh * 8 + r;
                xr[r] = (krow < NN && xjok) ? Xp[(long)krow * J + j0 + xjl] : 0.f;
            }
        }
        {
            const int cidx = lane & 3;
            const int rsel = lane >> 2;
            uint32_t ahi[2][4], alo[2][4];
#pragma unroll
            for (int mf = 0; mf < 2; mf++) {
                int r0 = m_base + mf * 16 + rsel;
                ahi[mf][0] = sS[buf][0][r0][cidx];
                ahi[mf][1] = sS[buf][0][r0 + 8][cidx];
                ahi[mf][2] = sS[buf][0][r0][cidx + 4];
                ahi[mf][3] = sS[buf][0][r0 + 8][cidx + 4];
                alo[mf][0] = sS[buf][1][r0][cidx];
                alo[mf][1] = sS[buf][1][r0 + 8][cidx];
                alo[mf][2] = sS[buf][1][r0][cidx + 4];
                alo[mf][3] = sS[buf][1][r0 + 8][cidx + 4];
            }
            uint32_t bhi[4][2], blo[4][2];
#pragma unroll
            for (int nf = 0; nf < 4; nf++) {
                int col = n_base + nf * 8 + rsel;
                bhi[nf][0] = sX[buf][0][col][cidx];
                bhi[nf][1] = sX[buf][0][col][cidx + 4];
                blo[nf][0] = sX[buf][1][col][cidx];
                blo[nf][1] = sX[buf][1][col][cidx + 4];
            }
#pragma unroll
            for (int mf = 0; mf < 2; mf++)
#pragma unroll
                for (int nf = 0; nf < 4; nf++) {
                    mma_bf16(c[mf][nf], ahi[mf][0], ahi[mf][1], ahi[mf][2], ahi[mf][3],
                             bhi[nf][0], bhi[nf][1]);
                    mma_bf16(c[mf][nf], ahi[mf][0], ahi[mf][1], ahi[mf][2], ahi[mf][3],
                             blo[nf][0], blo[nf][1]);
                    mma_bf16(c[mf][nf], alo[mf][0], alo[mf][1], alo[mf][2], alo[mf][3],
                             bhi[nf][0], bhi[nf][1]);
                }
        }
        __syncthreads();
        if (t + 1 < T) {
            const int nb = buf ^ 1;
            *reinterpret_cast<uint2*>(&sS[nb][0][sm][skq >> 1]) = sHiR;
            *reinterpret_cast<uint2*>(&sS[nb][1][sm][skq >> 1]) = sLoR;
#pragma unroll
            for (int pq = 0; pq < 4; pq++) {
                uint32_t lo;
                uint32_t hi = pack_hi2(xr[2 * pq], xr[2 * pq + 1], lo);
                sX[nb][0][xjl][xkh * 4 + pq] = hi;
                sX[nb][1][xjl][xkh * 4 + pq] = lo;
            }
            __syncthreads();
        }
    }

    {
        const int rsel = lane >> 2;
        const int csel = (lane & 3) * 2;
#pragma unroll
        for (int mf = 0; mf < 2; mf++) {
#pragma unroll
            for (int nf = 0; nf < 4; nf++) {
                int row = n0 + m_base + mf * 16 + rsel;
                int col = j0 + n_base + nf * 8 + csel;
                if (col < J) {
                    if (row < NN)
                        *reinterpret_cast<float2*>(&Yp[(long)row * J + col]) =
                            make_float2(c[mf][nf][0], c[mf][nf][1]);
                    if (row + 8 < NN)
                        *reinterpret_cast<float2*>(&Yp[(long)(row + 8) * J + col]) =
                            make_float2(c[mf][nf][2], c[mf][nf][3]);
                }
            }
        }
    }
}

// ---------------- tensor-core dense: D[b,o] = sum_k A[k,b] * W[k,o] ----------
__device__ __forceinline__ const float* feat_ptr(int k, int n, int Cx,
                                                 const float* x0x, const float* xcheb,
                                                 const float* h0, const float* hcheb) {
    int c = k / 5, m = k % 5;
    if (c < Cx)
        return (m == 0) ? (x0x + ((long)n * Cx + c) * BB)
                        : (xcheb + (((long)(m - 1) * NN + n) * Cx + c) * BB);
    int ch = c - Cx;
    return (m == 0) ? (h0 + ((long)n * HH + ch) * BB)
                    : (hcheb + (((long)(m - 1) * NN + n) * HH + ch) * BB);
}

__global__ void __launch_bounds__(256) dense_tc_kernel(
    const __nv_bfloat16* __restrict__ Wth, const __nv_bfloat16* __restrict__ Wtl,
    const float* __restrict__ x0x, const float* __restrict__ xcheb, int Cx,
    const float* __restrict__ h0, const float* __restrict__ hcheb,
    const float* __restrict__ bias, int O, int K, int mode,
    float* __restrict__ rh_out, float* __restrict__ u_out,
    const float* __restrict__ u_in, const float* __restrict__ h_old,
    float* __restrict__ h_new) {
    const int n = blockIdx.x;
    const int tid = threadIdx.x;
    const int lane = tid & 31;
    const int wid = tid >> 5;
    const int m_base = (wid & 1) * 32;   // b base
    const int o_base = (wid >> 1) * 32;  // o base

    // single-buffer smem, register prefetch; row stride 12 u32 (uint4-aligned)
    __shared__ uint32_t sA[2][64][12];
    __shared__ uint32_t sW[2][128][12];

    const int kp = tid & 7;          // k-pair index (2 bf16 = 1 u32)
    const int b0 = (tid >> 3) * 2;   // batch row base (2 rows)
    const int wo = tid >> 1;         // W o-row
    const int wq = (tid & 1) * 4;    // W u32 quad
    const uint32_t* WhU = reinterpret_cast<const uint32_t*>(Wth);
    const uint32_t* WlU = reinterpret_cast<const uint32_t*>(Wtl);

    float c[2][4][4];
#pragma unroll
    for (int mf = 0; mf < 2; mf++)
#pragma unroll
        for (int nf = 0; nf < 4; nf++)
#pragma unroll
            for (int q = 0; q < 4; q++) c[mf][nf][q] = 0.f;

    float2 va, vb;
    uint4 whR, wlR;

    // prefetch tile 0 into regs
    {
        int ka = 2 * kp, kb = ka + 1;
        va = (ka < K) ? *reinterpret_cast<const float2*>(
                            &feat_ptr(ka, n, Cx, x0x, xcheb, h0, hcheb)[b0])
                      : make_float2(0.f, 0.f);
        vb = (kb < K) ? *reinterpret_cast<const float2*>(
                            &feat_ptr(kb, n, Cx, x0x, xcheb, h0, hcheb)[b0])
                      : make_float2(0.f, 0.f);
        whR = *reinterpret_cast<const uint4*>(&WhU[(long)wo * WKP2 + wq]);
        wlR = *reinterpret_cast<const uint4*>(&WlU[(long)wo * WKP2 + wq]);
    }

    const int T = (K + KT - 1) / KT;
    for (int t = 0; t < T; t++) {
        // store regs -> smem
        {
            uint32_t lo0, hi0 = pack_hi2(va.x, vb.x, lo0);
            uint32_t lo1, hi1 = pack_hi2(va.y, vb.y, lo1);
            sA[0][b0][kp] = hi0;
            sA[1][b0][kp] = lo0;
            sA[0][b0 + 1][kp] = hi1;
            sA[1][b0 + 1][kp] = lo1;
            *reinterpret_cast<uint4*>(&sW[0][wo][wq]) = whR;
            *reinterpret_cast<uint4*>(&sW[1][wo][wq]) = wlR;
        }
        __syncthreads();
        // prefetch next tile
        if (t + 1 < T) {
            int k0 = (t + 1) * KT;
            int ka = k0 + 2 * kp, kb = ka + 1;
            va = (ka < K) ? *reinterpret_cast<const float2*>(
                                &feat_ptr(ka, n, Cx, x0x, xcheb, h0, hcheb)[b0])
                          : make_float2(0.f, 0.f);
            vb = (kb < K) ? *reinterpret_cast<const float2*>(
                                &feat_ptr(kb, n, Cx, x0x, xcheb, h0, hcheb)[b0])
                          : make_float2(0.f, 0.f);
            whR = *reinterpret_cast<const uint4*>(&WhU[(long)wo * WKP2 + (k0 >> 1) + wq]);
            wlR = *reinterpret_cast<const uint4*>(&WlU[(long)wo * WKP2 + (k0 >> 1) + wq]);
        }
        // mma on smem
        {
            const int cidx = lane & 3;
            const int rsel = lane >> 2;
            uint32_t ahi[2][4], alo[2][4];
#pragma unroll
            for (int mf = 0; mf < 2; mf++) {
                int r0 = m_base + mf * 16 + rsel;
                ahi[mf][0] = sA[0][r0][cidx];
                ahi[mf][1] = sA[0][r0 + 8][cidx];
                ahi[mf][2] = sA[0][r0][cidx + 4];
                ahi[mf][3] = sA[0][r0 + 8][cidx + 4];
                alo[mf][0] = sA[1][r0][cidx];
                alo[mf][1] = sA[1][r0 + 8][cidx];
                alo[mf][2] = sA[1][r0][cidx + 4];
                alo[mf][3] = sA[1][r0 + 8][cidx + 4];
            }
            uint32_t bhi[4][2], blo[4][2];
#pragma unroll
            for (int nf = 0; nf < 4; nf++) {
                int col = o_base + nf * 8 + rsel;
                bhi[nf][0] = sW[0][col][cidx];
                bhi[nf][1] = sW[0][col][cidx + 4];
                blo[nf][0] = sW[1][col][cidx];
                blo[nf][1] = sW[1][col][cidx + 4];
            }
#pragma unroll
            for (int mf = 0; mf < 2; mf++)
#pragma unroll
                for (int nf = 0; nf < 4; nf++) {
                    mma_bf16(c[mf][nf], ahi[mf][0], ahi[mf][1], ahi[mf][2], ahi[mf][3],
                             bhi[nf][0], bhi[nf][1]);
                    mma_bf16(c[mf][nf], ahi[mf][0], ahi[mf][1], ahi[mf][2], ahi[mf][3],
                             blo[nf][0], blo[nf][1]);
                    mma_bf16(c[mf][nf], alo[mf][0], alo[mf][1], alo[mf][2], alo[mf][3],
                             bhi[nf][0], bhi[nf][1]);
                }
        }
        __syncthreads();
    }

    // epilogue
    const int rsel = lane >> 2;
    const int csel = (lane & 3) * 2;
    if (mode == 0) {
#pragma unroll
        for (int mf = 0; mf < 2; mf++) {
#pragma unroll
            for (int nf = 0; nf < 4; nf++) {
                int o = o_base + nf * 8 + csel;
                if (o < O) {
                    float bo0 = bias[o], bo1 = bias[o + 1];
#pragma unroll
                    for (int e = 0; e < 4; e++) {
                        int b = m_base + mf * 16 + rsel + (e >> 1) * 8;
                        int oo = o + (e & 1);
                        float bo = (e & 1) ? bo1 : bo0;
                        float s = 1.f / (1.f + expf(-(c[mf][nf][e] + bo)));
                        if (oo < HH) {
                            long idx = ((long)n * HH + oo) * BB + b;
                            rh_out[idx] = s * h_old[idx];
                        } else {
                            u_out[((long)n * HH + (oo - HH)) * BB + b] = s;
                        }
                    }
                }
            }
        }
    } else {
#pragma unroll
        for (int mf = 0; mf < 2; mf++) {
#pragma unroll
            for (int nf = 0; nf < 4; nf++) {
                int o = o_base + nf * 8 + csel;
                if (o < O) {
                    float bo0 = bias[o], bo1 = bias[o + 1];
#pragma unroll
                    for (int e = 0; e < 4; e++) {
                        int b = m_base + mf * 16 + rsel + (e >> 1) * 8;
                        int oo = o + (e & 1);
                        float bo = (e & 1) ? bo1 : bo0;
                        long idx = ((long)n * HH + oo) * BB + b;
                        float uu = u_in[idx];
                        float hh = h_old[idx];
                        float cc = tanhf(c[mf][nf][e] + bo);
                        h_new[idx] = uu * hh + (1.f - uu) * cc;
                    }
                }
            }
        }
    }
}

// ---------------- final projection -------------------------------------------
__global__ void out_kernel(const float* __restrict__ h1, const float* __restrict__ Wfc,
                           const float* __restrict__ bfc, float* __restrict__ out) {
    int n = blockIdx.x;
    int b = threadIdx.x;
    float s = bfc[0];
    const float* hp = h1 + (long)n * HH * BB + b;
#pragma unroll
    for (int c = 0; c < HH; c++) s += hp[c * BB] * Wfc[c];
    out[(long)b * NN + n] = s;
}

// ---------------- host orchestration -----------------------------------------
static inline void smm_launch(const __nv_bfloat16* Shi, const __nv_bfloat16* Slo,
                              const float* X0, const float* X1,
                              float* Y0, float* Y1,
                              long slotstride, int J, int nz) {
    dim3 grid((J + 127) / 128, (NN + 63) / 64, nz);
    smm_tc_kernel<<<grid, 256>>>(Shi, Slo, X0, X1, Y0, Y1, slotstride, J);
}

extern "C" void kernel_launch(void* const* d_in, const int* in_sizes, int n_in,
                              void* d_out, int out_size) {
    const float* inputs = (const float*)d_in[0];
    const float* init_state = (const float*)d_in[1];
    const float* adj = (const float*)d_in[2];
    const float* Wg0 = (const float*)d_in[3];
    const float* bg0 = (const float*)d_in[4];
    const float* Wc0 = (const float*)d_in[5];
    const float* bc0 = (const float*)d_in[6];
    const float* Wg1 = (const float*)d_in[7];
    const float* bg1 = (const float*)d_in[8];
    const float* Wc1 = (const float*)d_in[9];
    const float* bc1 = (const float*)d_in[10];
    const float* Wfc = (const float*)d_in[11];
    const float* bfc = (const float*)d_in[12];
    float* out = (float*)d_out;

    void* p;
    cudaGetSymbolAddress(&p, g_M);      float* M = (float*)p;
    cudaGetSymbolAddress(&p, g_Shi);    __nv_bfloat16* Shi = (__nv_bfloat16*)p;
    cudaGetSymbolAddress(&p, g_Slo);    __nv_bfloat16* Slo = (__nv_bfloat16*)p;
    cudaGetSymbolAddress(&p, g_Wth);    __nv_bfloat16* Wth = (__nv_bfloat16*)p;
    cudaGetSymbolAddress(&p, g_Wtl);    __nv_bfloat16* Wtl = (__nv_bfloat16*)p;
    cudaGetSymbolAddress(&p, g_rs);     float* rs = (float*)p;
    cudaGetSymbolAddress(&p, g_cs);     float* cs = (float*)p;
    cudaGetSymbolAddress(&p, g_xx);     float* xx = (float*)p;
    cudaGetSymbolAddress(&p, g_xxcheb); float* xxcheb = (float*)p;
    cudaGetSymbolAddress(&p, g_x1cheb); float* x1cheb = (float*)p;
    cudaGetSymbolAddress(&p, g_hcheb);  float* hcheb = (float*)p;
    cudaGetSymbolAddress(&p, g_h0a);    float* h0a = (float*)p;
    cudaGetSymbolAddress(&p, g_h0b);    float* h0b = (float*)p;
    cudaGetSymbolAddress(&p, g_h1a);    float* h1a = (float*)p;
    cudaGetSymbolAddress(&p, g_h1b);    float* h1b = (float*)p;
    cudaGetSymbolAddress(&p, g_u);      float* u = (float*)p;
    cudaGetSymbolAddress(&p, g_rh);     float* rh = (float*)p;

    const long hs = (long)NN * HH * BB;
    const long xs0 = (long)NN * BB;
    const int nelem = NN * HH * BB;
    const long wsz = 128L * WKP;

    // one-time setup
    sums_kernel<<<(NN + 255) / 256, 256>>>(adj, rs, cs);
    build_S_kernel<<<(NN * NP + 255) / 256, 256>>>(adj, rs, cs, M);
    {
        dim3 g((NP + 15) / 16, (NN + 15) / 16, 2);
        ssq_kernel<<<g, dim3(16, 16)>>>(M, M + 2L * NN * NP);
    }
    split_kernel<<<(4 * NN * NP + 255) / 256, 256>>>(M, Shi, Slo, 4 * NN * NP);
    splitW_kernel<<<(128 * WKP + 255) / 256, 256>>>(Wg0, 325, 128, Wth, Wtl);
    splitW_kernel<<<(128 * WKP + 255) / 256, 256>>>(Wc0, 325, 64, Wth + wsz, Wtl + wsz);
    splitW_kernel<<<(128 * WKP + 255) / 256, 256>>>(Wg1, 640, 128, Wth + 2 * wsz, Wtl + 2 * wsz);
    splitW_kernel<<<(128 * WKP + 255) / 256, 256>>>(Wc1, 640, 64, Wth + 3 * wsz, Wtl + 3 * wsz);

    pack_state_kernel<<<(nelem + 255) / 256, 256>>>(init_state, h0a);
    pack_state_kernel<<<(nelem + 255) / 256, 256>>>(init_state + (long)BB * NN * HH, h1a);

    zero_kernel<<<(BB * NN + 255) / 256, 256>>>(out, BB * NN);

    for (int t = 0; t < 12; t++) {
        float* h0_old = (t & 1) ? h0b : h0a;
        float* h0_new = (t & 1) ? h0a : h0b;
        float* h1_old = (t & 1) ? h1b : h1a;
        float* h1_new = (t & 1) ? h1a : h1b;

        // ---- layer 0 ----
        pack_x_kernel<<<(NN * BB + 255) / 256, 256>>>(inputs + (long)t * BB * NN, xx);

        smm_launch(Shi, Slo, xx, 0, xxcheb, 0, xs0, BB, 4);

        // gate0
        smm_launch(Shi, Slo, h0_old, 0, hcheb, 0, hs, HH * BB, 4);
        dense_tc_kernel<<<NN, 256>>>(Wth, Wtl, xx, xxcheb, 1, h0_old, hcheb, bg0,
                                     128, 325, 0, rh, u, 0, h0_old, 0);

        // cand0
        smm_launch(Shi, Slo, rh, 0, hcheb, 0, hs, HH * BB, 4);
        dense_tc_kernel<<<NN, 256>>>(Wth + wsz, Wtl + wsz, xx, xxcheb, 1, rh, hcheb, bc0,
                                     64, 325, 1, 0, 0, u, h0_old, h0_new);

        // ---- layer 1: x1cheb (h0_new) + gate1 cheb (h1_old), z=8 ----
        smm_launch(Shi, Slo, h0_new, h1_old, x1cheb, hcheb, hs, HH * BB, 8);
        dense_tc_kernel<<<NN, 256>>>(Wth + 2 * wsz, Wtl + 2 * wsz, h0_new, x1cheb, HH,
                                     h1_old, hcheb, bg1, 128, 640, 0, rh, u, 0, h1_old, 0);

        // cand1
        smm_launch(Shi, Slo, rh, 0, hcheb, 0, hs, HH * BB, 4);
        dense_tc_kernel<<<NN, 256>>>(Wth + 3 * wsz, Wtl + 3 * wsz, h0_new, x1cheb, HH,
                                     rh, hcheb, bc1, 64, 640, 1, 0, 0, u, h1_old, h1_new);

        out_kernel<<<NN, BB>>>(h1_new, Wfc, bfc, out + (long)(t + 1) * BB * NN);
    }
}